// round 8
// baseline (speedup 1.0000x reference)
#include <cuda_runtime.h>
#include <cstdint>

#define T_STEPS 2048
#define BATCH   64
#define IN_DIM  128
#define HDIM    256
#define OUT_DIM 128
#define KTOT    384
#define NTHR    512
#define NBLK    128           // 16 groups (4 batch rows) x 8 ranks (32 h-cols)
#define CLUSTER 8
#define WOPAD   272

// smem layout (floats)
#define OFF_ACT   0                       // [2][384][4]  = 3072
#define OFF_WOUT  3072                    // [16][272]    = 4352
#define OFF_P     7424                    // [4][128][4]  = 2048
#define OFF_G     9472                    // [128][4]     = 512
#define OFF_BIAS  9984                    // 128
#define OFF_BOUT  10112                   // 16
#define OFF_STAGE 10128                   // [32][4]      = 128
#define OFF_MBAR  10256                   // 2 x u64 (byte off 41024, 8B aligned)
#define SMEM_FLOATS 10260
#define SMEM_BYTES (SMEM_FLOATS * 4)

#define EXCH_BYTES 4096    // 8 ranks x 32 cols x 16B per step

__device__ __forceinline__ void mbar_wait_parity(uint32_t mbar, uint32_t parity) {
    asm volatile(
        "{\n\t.reg .pred P;\n"
        "W0_%=: mbarrier.try_wait.parity.acquire.cta.shared::cta.b64 P, [%0], %1, 0x989680;\n\t"
        "@P bra W1_%=;\n\t"
        "bra W0_%=;\n"
        "W1_%=:\n\t}"
        :: "r"(mbar), "r"(parity) : "memory");
}

__global__ void __launch_bounds__(NTHR, 1) __cluster_dims__(CLUSTER, 1, 1)
lstm_dsmem_kernel(
    const float* __restrict__ input,   // [T, B, IN]
    const float* __restrict__ W_ih,    // [4H, IN]
    const float* __restrict__ W_hh,    // [4H, H]
    const float* __restrict__ b_ih,    // [4H]
    const float* __restrict__ b_hh,    // [4H]
    const float* __restrict__ W_out,   // [OUT, H]
    const float* __restrict__ b_out,   // [OUT]
    float* __restrict__ out,
    int out_size)
{
    extern __shared__ float sm[];
    float* sAct  = sm + OFF_ACT;   // [buf][k][r]: k<128 x, k>=128 h
    float* sWo   = sm + OFF_WOUT;
    float* sP    = sm + OFF_P;
    float* sG    = sm + OFF_G;
    float* sBias = sm + OFF_BIAS;
    float* sBOut = sm + OFF_BOUT;
    float* sStage= sm + OFF_STAGE;

    const int tid  = threadIdx.x;
    const int grp  = blockIdx.x >> 3;
    uint32_t rank;
    asm("mov.u32 %0, %%cluster_ctarank;" : "=r"(rank));
    const int rbase = grp * 4;
    const int cb    = (int)rank * 32;

    const uint32_t smB   = (uint32_t)__cvta_generic_to_shared(sm);
    const uint32_t mbarB = smB + OFF_MBAR * 4;

    // ---- gate-GEMM mapping: thread = (gate-col m, k-quarter kq) ----
    const int m   = tid & 127;
    const int kq  = tid >> 7;
    const int g_  = m >> 5;
    const int col = m & 31;
    const int kbase = kq * 96;
    const int grow  = g_ * HDIM + cb + col;

    // ---- weights into registers ----
    float wreg[96];
    {
        const float* src_ih = W_ih + (size_t)grow * IN_DIM;
        const float* src_hh = W_hh + (size_t)grow * HDIM - IN_DIM;
        #pragma unroll
        for (int i = 0; i < 96; i++) {
            int k = kbase + i;
            wreg[i] = (k < IN_DIM) ? __ldg(src_ih + k) : __ldg(src_hh + k);
        }
    }

    // ---- smem preload ----
    for (int i = tid; i < 16 * HDIM; i += NTHR) {
        int o = i >> 8, k = i & 255;
        sWo[o * WOPAD + k] = W_out[((int)rank * 16 + o) * HDIM + k];
    }
    if (tid < 128) sBias[tid] = b_ih[grow] + b_hh[grow];
    if (tid < 16) sBOut[tid] = b_out[(int)rank * 16 + tid];

    // zero both act buffers (h_0 = 0; x regions overwritten below)
    for (int i = tid; i < 2 * KTOT * 4; i += NTHR) sAct[i] = 0.0f;
    __syncthreads();
    if (tid < 128) {   // x_0 transposed into buf0
        int r = tid >> 5, k5 = tid & 31;
        float4 v = *(const float4*)(input + ((size_t)rbase + r) * IN_DIM + k5 * 4);
        sAct[(k5 * 4 + 0) * 4 + r] = v.x;
        sAct[(k5 * 4 + 1) * 4 + r] = v.y;
        sAct[(k5 * 4 + 2) * 4 + r] = v.z;
        sAct[(k5 * 4 + 3) * 4 + r] = v.w;
    }
    // init + pre-arm mbarriers (mbar[1] -> t=1, mbar[0] -> t=2)
    if (tid == 0) {
        asm volatile("mbarrier.init.shared.b64 [%0], 1;" :: "r"(mbarB) : "memory");
        asm volatile("mbarrier.init.shared.b64 [%0], 1;" :: "r"(mbarB + 8) : "memory");
        asm volatile("mbarrier.arrive.expect_tx.shared.b64 _, [%0], %1;"
                     :: "r"(mbarB), "r"(EXCH_BYTES) : "memory");
        asm volatile("mbarrier.arrive.expect_tx.shared.b64 _, [%0], %1;"
                     :: "r"(mbarB + 8), "r"(EXCH_BYTES) : "memory");
    }
    __syncthreads();
    asm volatile("barrier.cluster.arrive.aligned;" ::: "memory");
    asm volatile("barrier.cluster.wait.aligned;" ::: "memory");

    const size_t Y_TOTAL = (size_t)T_STEPS * BATCH * OUT_DIM;
    const bool write_tail = (out_size >= (int)(Y_TOTAL + 2 * BATCH * HDIM));

    float c_reg = 0.0f;   // cell state (r=tid>>5, col), threads 0-127

    for (int t = 0; t < T_STEPS; t++) {
        const int buf  = t & 1;
        const int bufn = 1 - buf;
        float* A = sAct + buf * (KTOT * 4);

        // ---- wait for h_t (t>0); re-arm this mbar for t+2 ----
        if (t > 0) {
            uint32_t parity = (uint32_t)(((t >> 1) - 1 + (t & 1)) & 1);
            mbar_wait_parity(mbarB + buf * 8, parity);
            if (tid == 0)
                asm volatile("mbarrier.arrive.expect_tx.shared.b64 _, [%0], %1;"
                             :: "r"(mbarB + buf * 8), "r"(EXCH_BYTES) : "memory");
        }

        // ---- gate GEMM: all 16 warps, f32x2, W in regs ----
        {
            const ulonglong2* av = (const ulonglong2*)(A + kbase * 4);
            unsigned long long acc01 = 0ULL, acc23 = 0ULL;
            #pragma unroll
            for (int i = 0; i < 96; i++) {
                ulonglong2 p = av[i];
                unsigned wu = __float_as_uint(wreg[i]);
                unsigned long long wp;
                asm("mov.b64 %0, {%1, %1};" : "=l"(wp) : "r"(wu));
                asm("fma.rn.f32x2 %0, %1, %2, %0;" : "+l"(acc01) : "l"(wp), "l"(p.x));
                asm("fma.rn.f32x2 %0, %1, %2, %0;" : "+l"(acc23) : "l"(wp), "l"(p.y));
            }
            unsigned u0, u1, u2, u3;
            asm("mov.b64 {%0, %1}, %2;" : "=r"(u0), "=r"(u1) : "l"(acc01));
            asm("mov.b64 {%0, %1}, %2;" : "=r"(u2), "=r"(u3) : "l"(acc23));
            *(float4*)(sP + (kq * 128 + m) * 4) =
                make_float4(__uint_as_float(u0), __uint_as_float(u1),
                            __uint_as_float(u2), __uint_as_float(u3));
        }
        __syncthreads();

        if (tid < 128) {
            // ---- reduce split-K + bias ----
            const float4* p4 = (const float4*)sP;
            float4 s0 = p4[tid], s1 = p4[128 + tid], s2 = p4[256 + tid], s3 = p4[384 + tid];
            float b = sBias[tid];
            *(float4*)(sG + tid * 4) = make_float4(
                s0.x + s1.x + s2.x + s3.x + b,
                s0.y + s1.y + s2.y + s3.y + b,
                s0.z + s1.z + s2.z + s3.z + b,
                s0.w + s1.w + s2.w + s3.w + b);
            asm volatile("bar.sync 1, 128;" ::: "memory");

            // ---- cell: thread (r = tid>>5, c = tid&31) ----
            const int r = tid >> 5, c = tid & 31;
            float gi = sG[(0 * 32 + c) * 4 + r];
            float gf = sG[(1 * 32 + c) * 4 + r];
            float gg = sG[(2 * 32 + c) * 4 + r];
            float go = sG[(3 * 32 + c) * 4 + r];
            float i_ = 1.0f / (1.0f + __expf(-gi));
            float f_ = 1.0f / (1.0f + __expf(-gf));
            float gv = tanhf(gg);
            float o_ = 1.0f / (1.0f + __expf(-go));
            float cn = f_ * c_reg + i_ * gv;
            float hn = o_ * tanhf(cn);
            c_reg = cn;

            sStage[c * 4 + r] = hn;
            if (t == T_STEPS - 1 && write_tail) {
                out[Y_TOTAL + (size_t)(rbase + r) * HDIM + cb + c] = hn;
                out[Y_TOTAL + BATCH * HDIM + (size_t)(rbase + r) * HDIM + cb + c] = cn;
            }
            asm volatile("bar.sync 1, 128;" ::: "memory");

            // ---- push h_{t+1} to all 8 peers' A[bufn] h-region via st.async ----
            {
                const int pq = tid >> 5;           // 2 peers per thread
                float4 hv = *(const float4*)(sStage + c * 4);
                uint32_t dloc = smB + (uint32_t)((bufn * KTOT + IN_DIM + cb + c) * 16);
                uint32_t mloc = mbarB + (uint32_t)(bufn * 8);
                #pragma unroll
                for (int e = 0; e < 2; e++) {
                    uint32_t p = (uint32_t)(pq * 2 + e);
                    uint32_t daddr, maddr;
                    asm("mapa.shared::cluster.u32 %0, %1, %2;" : "=r"(daddr) : "r"(dloc), "r"(p));
                    asm("mapa.shared::cluster.u32 %0, %1, %2;" : "=r"(maddr) : "r"(mloc), "r"(p));
                    asm volatile(
                        "st.async.weak.shared::cluster.mbarrier::complete_tx::bytes.v4.b32 "
                        "[%0], {%1, %2, %3, %4}, [%5];"
                        :: "r"(daddr),
                           "r"(__float_as_uint(hv.x)), "r"(__float_as_uint(hv.y)),
                           "r"(__float_as_uint(hv.z)), "r"(__float_as_uint(hv.w)),
                           "r"(maddr) : "memory");
                }
            }
        } else if (tid < 256) {
            // ---- warps 4-7: x_{t+1} prefetch (transposed) into A[bufn] ----
            if (t + 1 < T_STEPS) {
                int xr = (tid - 128) >> 5, xk5 = (tid - 128) & 31;
                float4 v = __ldcg((const float4*)(input
                            + ((size_t)(t + 1) * BATCH + rbase + xr) * IN_DIM + xk5 * 4));
                float* dst = sAct + bufn * (KTOT * 4);
                dst[(xk5 * 4 + 0) * 4 + xr] = v.x;
                dst[(xk5 * 4 + 1) * 4 + xr] = v.y;
                dst[(xk5 * 4 + 2) * 4 + xr] = v.z;
                dst[(xk5 * 4 + 3) * 4 + xr] = v.w;
            }
        } else if (t > 0) {
            // ---- warps 8-15: y_{t-1} = h_t @ W_out^T ----
            const int slot = tid - 256;
            const int o = slot >> 4, ks = slot & 15;
            float y0 = 0.f, y1 = 0.f, y2 = 0.f, y3 = 0.f;
            const float* wo = sWo + o * WOPAD + ks;
            const float4* ah = (const float4*)(A + (IN_DIM + ks) * 4);
            #pragma unroll
            for (int i = 0; i < 16; i++) {
                float w = wo[i * 16];
                float4 hv = ah[i * 16];
                y0 += w * hv.x; y1 += w * hv.y; y2 += w * hv.z; y3 += w * hv.w;
            }
            #pragma unroll
            for (int s = 1; s <= 8; s <<= 1) {
                y0 += __shfl_xor_sync(0xffffffffu, y0, s);
                y1 += __shfl_xor_sync(0xffffffffu, y1, s);
                y2 += __shfl_xor_sync(0xffffffffu, y2, s);
                y3 += __shfl_xor_sync(0xffffffffu, y3, s);
            }
            if (ks == 0) {
                float b = sBOut[o];
                size_t yb = ((size_t)(t - 1) * BATCH + rbase) * OUT_DIM
                            + (size_t)rank * 16 + o;
                out[yb + 0 * OUT_DIM] = y0 + b;
                out[yb + 1 * OUT_DIM] = y1 + b;
                out[yb + 2 * OUT_DIM] = y2 + b;
                out[yb + 3 * OUT_DIM] = y3 + b;
            }
        }
        __syncthreads();   // orders x-prefetch stores & y reads across steps
    }

    // ---- tail: wait final h push (mbar[0], use #1023 -> parity 1), y_{T-1} ----
    mbar_wait_parity(mbarB, 1u);
    if (tid >= 256) {
        const float* A = sAct;   // buf 0
        const int slot = tid - 256;
        const int o = slot >> 4, ks = slot & 15;
        float y0 = 0.f, y1 = 0.f, y2 = 0.f, y3 = 0.f;
        const float* wo = sWo + o * WOPAD + ks;
        const float4* ah = (const float4*)(A + (IN_DIM + ks) * 4);
        #pragma unroll
        for (int i = 0; i < 16; i++) {
            float w = wo[i * 16];
            float4 hv = ah[i * 16];
            y0 += w * hv.x; y1 += w * hv.y; y2 += w * hv.z; y3 += w * hv.w;
        }
        #pragma unroll
        for (int s = 1; s <= 8; s <<= 1) {
            y0 += __shfl_xor_sync(0xffffffffu, y0, s);
            y1 += __shfl_xor_sync(0xffffffffu, y1, s);
            y2 += __shfl_xor_sync(0xffffffffu, y2, s);
            y3 += __shfl_xor_sync(0xffffffffu, y3, s);
        }
        if (ks == 0) {
            float b = sBOut[o];
            size_t yb = ((size_t)(T_STEPS - 1) * BATCH + rbase) * OUT_DIM
                        + (size_t)rank * 16 + o;
            out[yb + 0 * OUT_DIM] = y0 + b;
            out[yb + 1 * OUT_DIM] = y1 + b;
            out[yb + 2 * OUT_DIM] = y2 + b;
            out[yb + 3 * OUT_DIM] = y3 + b;
        }
    }
    // no CTA exits while peers may still push into its smem
    asm volatile("barrier.cluster.arrive.aligned;" ::: "memory");
    asm volatile("barrier.cluster.wait.aligned;" ::: "memory");
}

extern "C" void kernel_launch(void* const* d_in, const int* in_sizes, int n_in,
                              void* d_out, int out_size) {
    const float* input = (const float*)d_in[0];
    const float* W_ih  = (const float*)d_in[1];
    const float* W_hh  = (const float*)d_in[2];
    const float* b_ih  = (const float*)d_in[3];
    const float* b_hh  = (const float*)d_in[4];
    const float* W_out = (const float*)d_in[5];
    const float* b_out = (const float*)d_in[6];
    float* out = (float*)d_out;
    (void)in_sizes; (void)n_in;

    cudaFuncSetAttribute(lstm_dsmem_kernel,
                         cudaFuncAttributeMaxDynamicSharedMemorySize, SMEM_BYTES);
    lstm_dsmem_kernel<<<NBLK, NTHR, SMEM_BYTES>>>(
        input, W_ih, W_hh, b_ih, b_hh, W_out, b_out, out, out_size);
}